// round 3
// baseline (speedup 1.0000x reference)
#include <cuda_runtime.h>

// EntropyLoss: heatmap [8, 20, 512, 512] f32 -> entropy [8] f32
//
// Per (n,c):  s = sum_{x>0} exp(x),  U = sum_{x>0} x*exp(x),  cnt = #positives
//             ent_c = (log s - U/s) / ln2          (max-shift cancels exactly)
// Per n:      out[n] = sum_c ent_c / sum_{c,hw} cnt
//
// Single fused kernel: streaming pass + last-block finalize (threadfence
// reduction pattern). Counter is reset by the finalizing block so every
// graph replay sees identical state -> deterministic.

#define N_BATCH   8
#define N_CH      20
#define CHANNELS  (N_BATCH * N_CH)   // 160
#define HW        (512 * 512)        // 262144
#define SPLIT     4                  // segments per channel
#define NBLK      (CHANNELS * SPLIT) // 640 blocks
#define SEG       (HW / SPLIT)       // 65536 elems
#define SEG4      (SEG / 4)          // 16384 float4
#define TPB       256

__device__ float g_ps[NBLK];        // partial sum exp(x)
__device__ float g_pU[NBLK];        // partial sum x*exp(x)
__device__ float g_pc[NBLK];        // partial positive count
__device__ unsigned int g_done = 0; // arrival counter (reset by last block)

__global__ void __launch_bounds__(TPB)
entropy_fused(const float* __restrict__ in, float* __restrict__ out)
{
    const int b   = blockIdx.x;
    const int ch  = b / SPLIT;        // 0..159
    const int seg = b % SPLIT;
    const float4* __restrict__ p4 =
        reinterpret_cast<const float4*>(in + (size_t)ch * HW + (size_t)seg * SEG);

    float s = 0.f, U = 0.f, cnt = 0.f;

    #pragma unroll 8
    for (int i = threadIdx.x; i < SEG4; i += TPB) {
        float4 v = p4[i];
        if (v.x > 0.f) { float e = __expf(v.x); s += e; U += v.x * e; cnt += 1.f; }
        if (v.y > 0.f) { float e = __expf(v.y); s += e; U += v.y * e; cnt += 1.f; }
        if (v.z > 0.f) { float e = __expf(v.z); s += e; U += v.z * e; cnt += 1.f; }
        if (v.w > 0.f) { float e = __expf(v.w); s += e; U += v.w * e; cnt += 1.f; }
    }

    // warp reduce
    #pragma unroll
    for (int o = 16; o > 0; o >>= 1) {
        s   += __shfl_down_sync(0xffffffffu, s,   o);
        U   += __shfl_down_sync(0xffffffffu, U,   o);
        cnt += __shfl_down_sync(0xffffffffu, cnt, o);
    }

    __shared__ float sh_s[TPB / 32], sh_U[TPB / 32], sh_c[TPB / 32];
    const int w = threadIdx.x >> 5;
    const int l = threadIdx.x & 31;
    if (l == 0) { sh_s[w] = s; sh_U[w] = U; sh_c[w] = cnt; }
    __syncthreads();

    __shared__ bool is_last;
    if (threadIdx.x == 0) {
        float ts = 0.f, tU = 0.f, tc = 0.f;
        #pragma unroll
        for (int i = 0; i < TPB / 32; i++) { ts += sh_s[i]; tU += sh_U[i]; tc += sh_c[i]; }
        g_ps[b] = ts; g_pU[b] = tU; g_pc[b] = tc;
        __threadfence();                       // publish partials before arrival
        unsigned int old = atomicAdd(&g_done, 1u);
        is_last = (old == NBLK - 1);
    }
    __syncthreads();
    if (!is_last) return;

    // ---- finalize: only the last-arriving block runs this ----
    __threadfence();                           // acquire: see all partials

    __shared__ float ent_c[CHANNELS];
    __shared__ float cnt_c[CHANNELS];

    const int t = threadIdx.x;
    if (t == 0) g_done = 0;                    // reset for next replay
    if (t < CHANNELS) {
        float ss = 0.f, UU = 0.f, cc = 0.f;
        #pragma unroll
        for (int k = 0; k < SPLIT; k++) {
            ss += g_ps[t * SPLIT + k];
            UU += g_pU[t * SPLIT + k];
            cc += g_pc[t * SPLIT + k];
        }
        float ent = 0.f;
        if (ss > 0.f) {
            const float INV_LN2 = 1.4426950408889634f;
            ent = (logf(ss) - UU / ss) * INV_LN2;
        }
        ent_c[t] = ent;
        cnt_c[t] = cc;
    }
    __syncthreads();

    if (t < N_BATCH) {
        float es = 0.f, cs = 0.f;
        #pragma unroll
        for (int c = 0; c < N_CH; c++) {
            es += ent_c[t * N_CH + c];
            cs += cnt_c[t * N_CH + c];
        }
        out[t] = es / cs;
    }
}

extern "C" void kernel_launch(void* const* d_in, const int* in_sizes, int n_in,
                              void* d_out, int out_size)
{
    const float* heatmap = (const float*)d_in[0];
    float* out = (float*)d_out;
    entropy_fused<<<NBLK, TPB>>>(heatmap, out);
}

// round 4
// speedup vs baseline: 1.1221x; 1.1221x over previous
#include <cuda_runtime.h>

// EntropyLoss: heatmap [8, 20, 512, 512] f32 -> entropy [8] f32
//
// Per (n,c):  s = sum_{x>0} exp(x),  U = sum_{x>0} x*exp(x),  cnt = #positives
//             ent_c = (log s - U/s) / ln2          (max-shift cancels exactly)
// Per n:      out[n] = sum_c ent_c / sum_{c,hw} cnt
//
// SPLIT=7 -> 1120 blocks x 256 thr = 287K threads (94.6% occupancy), all
// resident in a single wave at <=32 regs/thread (enforced by launch bounds).
// Fused last-block finalize via threadfence-reduction; counter self-resets
// so graph replays are deterministic.

#define N_BATCH   8
#define N_CH      20
#define CHANNELS  (N_BATCH * N_CH)   // 160
#define HW        (512 * 512)        // 262144 elems/channel
#define HW4       (HW / 4)           // 65536 float4/channel
#define SPLIT     7                  // segments per channel
#define NBLK      (CHANNELS * SPLIT) // 1120 blocks
#define TPB       256

__device__ float g_ps[NBLK];        // partial sum exp(x)
__device__ float g_pU[NBLK];        // partial sum x*exp(x)
__device__ float g_pc[NBLK];        // partial positive count
__device__ unsigned int g_done = 0; // arrival counter (reset by last block)

__global__ void __launch_bounds__(TPB, 8)
entropy_fused(const float* __restrict__ in, float* __restrict__ out)
{
    const int b   = blockIdx.x;
    const int ch  = b / SPLIT;        // 0..159
    const int seg = b % SPLIT;
    const int i0  = (HW4 * seg) / SPLIT;        // float4 range within channel
    const int i1  = (HW4 * (seg + 1)) / SPLIT;
    const float4* __restrict__ p4 =
        reinterpret_cast<const float4*>(in + (size_t)ch * HW);

    float s = 0.f, U = 0.f, cnt = 0.f;

    #pragma unroll 4
    for (int i = i0 + threadIdx.x; i < i1; i += TPB) {
        float4 v = p4[i];
        if (v.x > 0.f) { float e = __expf(v.x); s += e; U += v.x * e; cnt += 1.f; }
        if (v.y > 0.f) { float e = __expf(v.y); s += e; U += v.y * e; cnt += 1.f; }
        if (v.z > 0.f) { float e = __expf(v.z); s += e; U += v.z * e; cnt += 1.f; }
        if (v.w > 0.f) { float e = __expf(v.w); s += e; U += v.w * e; cnt += 1.f; }
    }

    // warp reduce
    #pragma unroll
    for (int o = 16; o > 0; o >>= 1) {
        s   += __shfl_down_sync(0xffffffffu, s,   o);
        U   += __shfl_down_sync(0xffffffffu, U,   o);
        cnt += __shfl_down_sync(0xffffffffu, cnt, o);
    }

    __shared__ float sh_s[TPB / 32], sh_U[TPB / 32], sh_c[TPB / 32];
    const int w = threadIdx.x >> 5;
    const int l = threadIdx.x & 31;
    if (l == 0) { sh_s[w] = s; sh_U[w] = U; sh_c[w] = cnt; }
    __syncthreads();

    __shared__ bool is_last;
    if (threadIdx.x == 0) {
        float ts = 0.f, tU = 0.f, tc = 0.f;
        #pragma unroll
        for (int i = 0; i < TPB / 32; i++) { ts += sh_s[i]; tU += sh_U[i]; tc += sh_c[i]; }
        g_ps[b] = ts; g_pU[b] = tU; g_pc[b] = tc;
        __threadfence();                       // publish partials before arrival
        unsigned int old = atomicAdd(&g_done, 1u);
        is_last = (old == NBLK - 1);
    }
    __syncthreads();
    if (!is_last) return;

    // ---- finalize: only the last-arriving block runs this ----
    __threadfence();                           // acquire: see all partials

    __shared__ float ent_c[CHANNELS];
    __shared__ float cnt_c[CHANNELS];

    const int t = threadIdx.x;
    if (t == 0) g_done = 0;                    // reset for next graph replay
    if (t < CHANNELS) {
        float ss = 0.f, UU = 0.f, cc = 0.f;
        #pragma unroll
        for (int k = 0; k < SPLIT; k++) {
            ss += g_ps[t * SPLIT + k];
            UU += g_pU[t * SPLIT + k];
            cc += g_pc[t * SPLIT + k];
        }
        float ent = 0.f;
        if (ss > 0.f) {
            const float INV_LN2 = 1.4426950408889634f;
            ent = (logf(ss) - UU / ss) * INV_LN2;
        }
        ent_c[t] = ent;
        cnt_c[t] = cc;
    }
    __syncthreads();

    if (t < N_BATCH) {
        float es = 0.f, cs = 0.f;
        #pragma unroll
        for (int c = 0; c < N_CH; c++) {
            es += ent_c[t * N_CH + c];
            cs += cnt_c[t * N_CH + c];
        }
        out[t] = es / cs;
    }
}

extern "C" void kernel_launch(void* const* d_in, const int* in_sizes, int n_in,
                              void* d_out, int out_size)
{
    const float* heatmap = (const float*)d_in[0];
    float* out = (float*)d_out;
    entropy_fused<<<NBLK, TPB>>>(heatmap, out);
}